// round 11
// baseline (speedup 1.0000x reference)
#include <cuda_runtime.h>
#include <cuda_fp16.h>
#include <math.h>
#include <stdint.h>

// ---------------- problem constants ----------------
#define NN   10000
#define NE   320000
#define FDIM 256
#define CAP  128          // fixed per-row CSR capacity (E[deg]=32, max ~60)

#define BM_QUADS 781250   // 10000*10000 bits in uint4

// grid-level specialization: 79 GEMM CTAs + 69 worker CTAs = 148 = one wave
#define N_GEMM 79
#define N_WORK 69
#define NBLK   (N_GEMM + N_WORK)
#define THREADS 512
#define NWARPS_TOTAL (NBLK * (THREADS / 32))   // 2368

// ---------------- device scratch ----------------
__device__ uint4   g_bitmap4[BM_QUADS];
__device__ int     g_rowcnt[NN];
__device__ int     g_deg[NN];
__device__ int     g_col[NN * CAP];          // 5.12 MB
__device__ float   g_Ps[NN * FDIM];          // dinv[m]*(X@W)[m], fp32 (self term)
__device__ __half  g_Ph[NN * FDIM];          // dinv[m]*(X@W)[m], fp16 (gather term)
__device__ int     g_c_clear;                // monotonic, reset post-barrier
__device__ int     g_c_work;                 // monotonic, reset post-barrier
__device__ int     g_bar_cnt;                // self-resetting
__device__ int     g_bar_sense;              // toggles each call (persistent)

// ---------------- GEMM config: 128x256x32, 16 warps 4(m)x4(n), warp 32x64 ----------------
#define BMT 128
#define BNT 256
#define BKT 32
#define A_LD (BKT + 4)
#define B_LD (BNT + 8)
#define A_BYTES (BMT * A_LD * 4)
#define B_BYTES (BKT * B_LD * 4)
#define BUF_BYTES (A_BYTES + B_BYTES)
#define SMEM_TOTAL (2 * BUF_BYTES)           // 104448

__device__ __forceinline__ uint32_t smem_u32(const void* p) {
    uint32_t a;
    asm("{ .reg .u64 t; cvta.to.shared.u64 t, %1; cvt.u32.u64 %0, t; }" : "=r"(a) : "l"(p));
    return a;
}
#define CP_ASYNC16(dst, src, szr) \
    asm volatile("cp.async.cg.shared.global [%0], [%1], 16, %2;" \
        :: "r"(dst), "l"(src), "r"(szr))
#define CP_COMMIT() asm volatile("cp.async.commit_group;" ::: "memory")
#define CP_WAIT(n)  asm volatile("cp.async.wait_group %0;" :: "n"(n) : "memory")

__device__ __forceinline__ uint32_t rna(uint32_t x) {
    float r; asm("cvt.rna.tf32.f32 %0, %1;" : "=f"(r) : "f"(__uint_as_float(x)));
    return __float_as_uint(r);
}
__device__ __forceinline__ void mma_tf32(float c[4],
                                         uint32_t a0, uint32_t a1, uint32_t a2, uint32_t a3,
                                         uint32_t b0, uint32_t b1) {
    asm volatile(
        "mma.sync.aligned.m16n8k8.row.col.f32.tf32.tf32.f32 "
        "{%0,%1,%2,%3}, {%4,%5,%6,%7}, {%8,%9}, {%0,%1,%2,%3};"
        : "+f"(c[0]), "+f"(c[1]), "+f"(c[2]), "+f"(c[3])
        : "r"(a0), "r"(a1), "r"(a2), "r"(a3), "r"(b0), "r"(b1));
}

// all-CTA sense-reversing barrier (count self-resets; sense toggles per call)
__device__ __forceinline__ void barrier_all() {
    __syncthreads();
    if (threadIdx.x == 0) {
        int s0 = *(volatile int*)&g_bar_sense;   // flip can't precede own arrival
        __threadfence();
        int old = atomicAdd(&g_bar_cnt, 1);
        if (old == NBLK - 1) {
            g_bar_cnt = 0;
            __threadfence();
            atomicExch(&g_bar_sense, s0 ^ 1);
        } else {
            while (*(volatile int*)&g_bar_sense == s0) __nanosleep(32);
        }
        __threadfence();
    }
    __syncthreads();
}

// ---------------- persistent kernel: GEMM || (clear->dedup) -> barrier -> aggregate ----------------
__global__ __launch_bounds__(THREADS, 1) void k_fused(const float* __restrict__ X,
                                                      const float* __restrict__ W,
                                                      const int* __restrict__ src,
                                                      const int* __restrict__ tgt,
                                                      float* __restrict__ out) {
    int tid = threadIdx.x;

    if (blockIdx.x >= N_GEMM) {
        // ===== worker role: clear, barrier(workers), dedup + CSR fill =====
        int gt = (blockIdx.x - N_GEMM) * THREADS + tid;
        const int nthr = N_WORK * THREADS;

        uint4 z = make_uint4(0u, 0u, 0u, 0u);
        for (int w = gt; w < BM_QUADS; w += nthr) g_bitmap4[w] = z;
        for (int j = gt; j < NN; j += nthr) { g_rowcnt[j] = 0; g_deg[j] = 0; }
        __threadfence();
        __syncthreads();
        if (tid == 0) {
            atomicAdd(&g_c_clear, 1);
            while (*(volatile int*)&g_c_clear < N_WORK) __nanosleep(64);
        }
        __syncthreads();

        unsigned int* bm = reinterpret_cast<unsigned int*>(g_bitmap4);
        const int nq = NE / 4;
        for (int i = gt; i < nq; i += nthr) {
            int4 s4 = reinterpret_cast<const int4*>(src)[i];
            int4 t4 = reinterpret_cast<const int4*>(tgt)[i];
            int ss[4] = {s4.x, s4.y, s4.z, s4.w};
            int tt[4] = {t4.x, t4.y, t4.z, t4.w};
            #pragma unroll
            for (int j = 0; j < 4; j++) {
                int s = ss[j], t = tt[j];
                unsigned int bit  = (unsigned int)s * (unsigned int)NN + (unsigned int)t;
                unsigned int word = bit >> 5;
                unsigned int mask = 1u << (bit & 31u);
                unsigned int old  = atomicOr(&bm[word], mask);
                if (!(old & mask)) {
                    int pos = atomicAdd(&g_rowcnt[s], 1);
                    if (pos < CAP) g_col[s * CAP + pos] = t;
                    atomicAdd(&g_deg[t], 1);
                }
            }
        }
        __threadfence();
        __syncthreads();
        if (tid == 0) atomicAdd(&g_c_work, 1);
    } else {
        // ===== GEMM role =====
        extern __shared__ char sm[];
        int wid  = tid >> 5;
        int lane = tid & 31;
        int g    = lane >> 2;
        int t    = lane & 3;
        int bm0  = blockIdx.x * BMT;
        int wm   = (wid >> 2) * 32;
        int wn   = (wid & 3)  * 64;

        int a_row0 = tid >> 3,         a_c4_0 = tid & 7;
        int a_row1 = (tid + 512) >> 3, a_c4_1 = (tid + 512) & 7;

        auto issue_tile = [&](int k0, int buf) {
            uint32_t sA = smem_u32(sm + buf * BUF_BYTES);
            uint32_t sB = sA + A_BYTES;
            {
                int gr = bm0 + a_row0;
                uint32_t dst = sA + (a_row0 * A_LD + a_c4_0 * 4) * 4;
                const float* srcp = &X[(size_t)gr * FDIM + k0 + a_c4_0 * 4];
                CP_ASYNC16(dst, srcp, (gr < NN) ? 16 : 0);
                gr = bm0 + a_row1;
                dst = sA + (a_row1 * A_LD + a_c4_1 * 4) * 4;
                srcp = &X[(size_t)gr * FDIM + k0 + a_c4_1 * 4];
                CP_ASYNC16(dst, srcp, (gr < NN) ? 16 : 0);
            }
            #pragma unroll
            for (int p = 0; p < 4; p++) {
                int id  = p * 512 + tid;
                int row = id >> 6;
                int c4  = id & 63;
                uint32_t dst = sB + (row * B_LD + c4 * 4) * 4;
                const float* srcp = &W[(size_t)(k0 + row) * FDIM + c4 * 4];
                CP_ASYNC16(dst, srcp, 16);
            }
            CP_COMMIT();
        };

        float acc[2][8][4];
        #pragma unroll
        for (int mt = 0; mt < 2; mt++)
            #pragma unroll
            for (int nt = 0; nt < 8; nt++)
                #pragma unroll
                for (int q = 0; q < 4; q++) acc[mt][nt][q] = 0.0f;

        issue_tile(0, 0);

        #pragma unroll 1
        for (int ki = 0; ki < FDIM / BKT; ki++) {
            int buf = ki & 1;
            if (ki + 1 < FDIM / BKT) { issue_tile((ki + 1) * BKT, buf ^ 1); CP_WAIT(1); }
            else                     { CP_WAIT(0); }
            __syncthreads();

            const uint32_t* As = reinterpret_cast<const uint32_t*>(sm + buf * BUF_BYTES);
            const uint32_t* Bs = reinterpret_cast<const uint32_t*>(sm + buf * BUF_BYTES + A_BYTES);

            #pragma unroll
            for (int ks = 0; ks < BKT / 8; ks++) {
                int kb = ks * 8;
                uint32_t a[2][4];
                #pragma unroll
                for (int mt = 0; mt < 2; mt++) {
                    int r0 = wm + mt * 16;
                    a[mt][0] = rna(As[(r0 + g    ) * A_LD + kb + t    ]);
                    a[mt][1] = rna(As[(r0 + g + 8) * A_LD + kb + t    ]);
                    a[mt][2] = rna(As[(r0 + g    ) * A_LD + kb + t + 4]);
                    a[mt][3] = rna(As[(r0 + g + 8) * A_LD + kb + t + 4]);
                }
                uint32_t b[8][2];
                #pragma unroll
                for (int nt = 0; nt < 8; nt++) {
                    int col = wn + nt * 8 + g;
                    b[nt][0] = rna(Bs[(kb + t    ) * B_LD + col]);
                    b[nt][1] = rna(Bs[(kb + t + 4) * B_LD + col]);
                }
                #pragma unroll
                for (int mt = 0; mt < 2; mt++)
                    #pragma unroll
                    for (int nt = 0; nt < 8; nt++)
                        mma_tf32(acc[mt][nt], a[mt][0], a[mt][1], a[mt][2], a[mt][3],
                                 b[nt][0], b[nt][1]);
            }
            __syncthreads();
        }

        // wait for workers' deg, then pre-scale + store fp32/fp16 copies
        if (tid == 0)
            while (*(volatile int*)&g_c_work < N_WORK) __nanosleep(64);
        __syncthreads();
        __threadfence();

        #pragma unroll
        for (int mt = 0; mt < 2; mt++) {
            #pragma unroll
            for (int half = 0; half < 2; half++) {
                int gm = bm0 + wm + mt * 16 + g + half * 8;
                if (gm >= NN) continue;
                float dm = rsqrtf((float)(g_deg[gm] + 1));
                #pragma unroll
                for (int nt = 0; nt < 8; nt++) {
                    float c0 = dm * acc[mt][nt][half * 2 + 0];
                    float c1 = dm * acc[mt][nt][half * 2 + 1];
                    int gc = wn + nt * 8 + t * 2;
                    *reinterpret_cast<float2*>(&g_Ps[(size_t)gm * FDIM + gc]) = make_float2(c0, c1);
                    *reinterpret_cast<__half2*>(&g_Ph[(size_t)gm * FDIM + gc]) =
                        __float22half2_rn(make_float2(c0, c1));
                }
            }
        }
        __threadfence();
    }

    // ===== global barrier, counter reset, then aggregation by ALL CTAs =====
    barrier_all();
    if (blockIdx.x == 0 && tid == 0) { g_c_clear = 0; g_c_work = 0; __threadfence(); }

    int gwarp = blockIdx.x * (THREADS / 32) + (tid >> 5);
    int lane  = tid & 31;

    for (int row = gwarp; row < NN; row += NWARPS_TOTAL) {
        // self term (pre-scaled fp32), 8 cols/lane
        const float4* pr = reinterpret_cast<const float4*>(g_Ps + (size_t)row * FDIM) + lane * 2;
        float4 p0 = pr[0], p1 = pr[1];
        float a0 = p0.x, a1 = p0.y, a2 = p0.z, a3 = p0.w;
        float a4 = p1.x, a5 = p1.y, a6 = p1.z, a7 = p1.w;

        int len = g_rowcnt[row];
        if (len > CAP) len = CAP;
        const int*  cols = g_col + row * CAP;
        const int4* c4p  = reinterpret_cast<const int4*>(cols);

        int nq8 = len >> 3;                 // groups of 8 neighbors
        int4 ca, cb;
        if (nq8 > 0) { ca = c4p[0]; cb = c4p[1]; }

        for (int q = 0; q < nq8; q++) {
            int4 cc = ca, cd = cb;
            if (q + 1 < nq8) { ca = c4p[2 * q + 2]; cb = c4p[2 * q + 3]; }
            // 8 independent gathers (MLP 8)
            uint4 h0 = *(reinterpret_cast<const uint4*>(g_Ph + (size_t)cc.x * FDIM) + lane);
            uint4 h1 = *(reinterpret_cast<const uint4*>(g_Ph + (size_t)cc.y * FDIM) + lane);
            uint4 h2 = *(reinterpret_cast<const uint4*>(g_Ph + (size_t)cc.z * FDIM) + lane);
            uint4 h3 = *(reinterpret_cast<const uint4*>(g_Ph + (size_t)cc.w * FDIM) + lane);
            uint4 h4 = *(reinterpret_cast<const uint4*>(g_Ph + (size_t)cd.x * FDIM) + lane);
            uint4 h5 = *(reinterpret_cast<const uint4*>(g_Ph + (size_t)cd.y * FDIM) + lane);
            uint4 h6 = *(reinterpret_cast<const uint4*>(g_Ph + (size_t)cd.z * FDIM) + lane);
            uint4 h7 = *(reinterpret_cast<const uint4*>(g_Ph + (size_t)cd.w * FDIM) + lane);
            // 1-level fp16 pairing, fp32 accumulate
            #pragma unroll
            for (int pr2 = 0; pr2 < 4; pr2++) {
                const uint4& x = (pr2 == 0) ? h0 : (pr2 == 1) ? h2 : (pr2 == 2) ? h4 : h6;
                const uint4& y = (pr2 == 0) ? h1 : (pr2 == 1) ? h3 : (pr2 == 2) ? h5 : h7;
                __half2 s0 = __hadd2(*reinterpret_cast<const __half2*>(&x.x),
                                     *reinterpret_cast<const __half2*>(&y.x));
                __half2 s1 = __hadd2(*reinterpret_cast<const __half2*>(&x.y),
                                     *reinterpret_cast<const __half2*>(&y.y));
                __half2 s2 = __hadd2(*reinterpret_cast<const __half2*>(&x.z),
                                     *reinterpret_cast<const __half2*>(&y.z));
                __half2 s3 = __hadd2(*reinterpret_cast<const __half2*>(&x.w),
                                     *reinterpret_cast<const __half2*>(&y.w));
                float2 f;
                f = __half22float2(s0); a0 += f.x; a1 += f.y;
                f = __half22float2(s1); a2 += f.x; a3 += f.y;
                f = __half22float2(s2); a4 += f.x; a5 += f.y;
                f = __half22float2(s3); a6 += f.x; a7 += f.y;
            }
        }
        // tail (<8), plain fp32
        for (int i = nq8 * 8; i < len; i++) {
            uint4 h = *(reinterpret_cast<const uint4*>(g_Ph + (size_t)cols[i] * FDIM) + lane);
            float2 f;
            f = __half22float2(*reinterpret_cast<const __half2*>(&h.x)); a0 += f.x; a1 += f.y;
            f = __half22float2(*reinterpret_cast<const __half2*>(&h.y)); a2 += f.x; a3 += f.y;
            f = __half22float2(*reinterpret_cast<const __half2*>(&h.z)); a4 += f.x; a5 += f.y;
            f = __half22float2(*reinterpret_cast<const __half2*>(&h.w)); a6 += f.x; a7 += f.y;
        }

        float dr = rsqrtf((float)(g_deg[row] + 1));
        float4 o0 = make_float4(fmaxf(dr * a0, 0.f), fmaxf(dr * a1, 0.f),
                                fmaxf(dr * a2, 0.f), fmaxf(dr * a3, 0.f));
        float4 o1 = make_float4(fmaxf(dr * a4, 0.f), fmaxf(dr * a5, 0.f),
                                fmaxf(dr * a6, 0.f), fmaxf(dr * a7, 0.f));
        float4* po = reinterpret_cast<float4*>(out + (size_t)row * FDIM) + lane * 2;
        po[0] = o0; po[1] = o1;
    }
}

// ---------------- launch ----------------
extern "C" void kernel_launch(void* const* d_in, const int* in_sizes, int n_in,
                              void* d_out, int out_size) {
    const float* X = (const float*)d_in[0];             // [10000, 256]
    const float* W = (const float*)d_in[1];             // [256, 256]
    const int*   E = (const int*)d_in[2];               // [2, 320000]
    const int* src = E;
    const int* tgt = E + NE;
    float* out = (float*)d_out;

    cudaFuncSetAttribute(k_fused, cudaFuncAttributeMaxDynamicSharedMemorySize, SMEM_TOTAL);
    k_fused<<<NBLK, THREADS, SMEM_TOTAL>>>(X, W, src, tgt, out);   // 148 CTAs = one wave
}

// round 14
// speedup vs baseline: 1.0769x; 1.0769x over previous
#include <cuda_runtime.h>
#include <cuda_fp16.h>
#include <math.h>
#include <stdint.h>

// ---------------- problem constants ----------------
#define NN   10000
#define NE   320000
#define FDIM 256
#define CAP  128          // fixed per-row CSR capacity (E[deg]=32, max ~60)

#define BM_QUADS 781250   // 10000*10000 bits as uint4

// grid: workers at low bids (guaranteed wave-1), GEMM tiles after
#define N_WORK  138
#define N_MT    157                       // ceil(10000/64)
#define N_GEMM  (N_MT * 2)                // 314 tiles of 64x128
#define NBLK    (N_WORK + N_GEMM)         // 452
#define THREADS 256

// ---------------- device scratch ----------------
__device__ uint4   g_bitmap4[BM_QUADS];
__device__ int     g_rowcnt[NN];
__device__ int     g_deg[NN];
__device__ int     g_col[NN * CAP];          // 5.12 MB
__device__ float   g_Ps[NN * FDIM];          // dinv[m]*(X@W)[m], fp32 (self term)
__device__ __half  g_Ph[NN * FDIM];          // dinv[m]*(X@W)[m], fp16 (gather term)
__device__ int     g_c_clear;                // reset by k_aggregate
__device__ int     g_c_work;                 // reset by k_aggregate

// ---------------- GEMM config: 64x128x32, 8 warps 2(m)x4(n), warp 32x32 ----------------
#define BMT 64
#define BNT 128
#define BKT 32
#define A_LD (BKT + 4)                        // 36
#define B_LD (BNT + 8)                        // 136
#define A_BYTES (BMT * A_LD * 4)              // 9216
#define B_BYTES (BKT * B_LD * 4)              // 17408
#define BUF_BYTES (A_BYTES + B_BYTES)         // 26624
#define SMEM_TOTAL (2 * BUF_BYTES)            // 53248

__device__ __forceinline__ uint32_t smem_u32(const void* p) {
    uint32_t a;
    asm("{ .reg .u64 t; cvta.to.shared.u64 t, %1; cvt.u32.u64 %0, t; }" : "=r"(a) : "l"(p));
    return a;
}
#define CP_ASYNC16(dst, src, szr) \
    asm volatile("cp.async.cg.shared.global [%0], [%1], 16, %2;" \
        :: "r"(dst), "l"(src), "r"(szr))
#define CP_COMMIT() asm volatile("cp.async.commit_group;" ::: "memory")
#define CP_WAIT(n)  asm volatile("cp.async.wait_group %0;" :: "n"(n) : "memory")

__device__ __forceinline__ uint32_t rna(uint32_t x) {
    float r; asm("cvt.rna.tf32.f32 %0, %1;" : "=f"(r) : "f"(__uint_as_float(x)));
    return __float_as_uint(r);
}
__device__ __forceinline__ void mma_tf32(float c[4],
                                         uint32_t a0, uint32_t a1, uint32_t a2, uint32_t a3,
                                         uint32_t b0, uint32_t b1) {
    asm volatile(
        "mma.sync.aligned.m16n8k8.row.col.f32.tf32.tf32.f32 "
        "{%0,%1,%2,%3}, {%4,%5,%6,%7}, {%8,%9}, {%0,%1,%2,%3};"
        : "+f"(c[0]), "+f"(c[1]), "+f"(c[2]), "+f"(c[3])
        : "r"(a0), "r"(a1), "r"(a2), "r"(a3), "r"(b0), "r"(b1));
}

// ---------------- fused: worker CTAs (clear->dedup) || GEMM CTAs ----------------
__global__ __launch_bounds__(THREADS, 3) void k_fused(const float* __restrict__ X,
                                                      const float* __restrict__ W,
                                                      const int* __restrict__ src,
                                                      const int* __restrict__ tgt) {
    int tid = threadIdx.x;

    if (blockIdx.x < N_WORK) {
        // ===== worker role: clear, barrier(workers), dedup + CSR fill =====
        int gt = blockIdx.x * THREADS + tid;
        const int nthr = N_WORK * THREADS;               // 35328

        uint4 z = make_uint4(0u, 0u, 0u, 0u);
        for (int w = gt; w < BM_QUADS; w += nthr) g_bitmap4[w] = z;
        for (int j = gt; j < NN; j += nthr) { g_rowcnt[j] = 0; g_deg[j] = 0; }
        __threadfence();
        __syncthreads();
        if (tid == 0) {
            atomicAdd(&g_c_clear, 1);
            while (*(volatile int*)&g_c_clear < N_WORK) __nanosleep(64);
        }
        __syncthreads();

        unsigned int* bm = reinterpret_cast<unsigned int*>(g_bitmap4);
        const int nq = NE / 4;
        for (int i = gt; i < nq; i += nthr) {
            int4 s4 = reinterpret_cast<const int4*>(src)[i];
            int4 t4 = reinterpret_cast<const int4*>(tgt)[i];
            int ss[4] = {s4.x, s4.y, s4.z, s4.w};
            int tt[4] = {t4.x, t4.y, t4.z, t4.w};
            #pragma unroll
            for (int j = 0; j < 4; j++) {
                int s = ss[j], t = tt[j];
                unsigned int bit  = (unsigned int)s * (unsigned int)NN + (unsigned int)t;
                unsigned int word = bit >> 5;
                unsigned int mask = 1u << (bit & 31u);
                unsigned int old  = atomicOr(&bm[word], mask);
                if (!(old & mask)) {
                    int pos = atomicAdd(&g_rowcnt[s], 1);
                    if (pos < CAP) g_col[s * CAP + pos] = t;
                    atomicAdd(&g_deg[t], 1);
                }
            }
        }
        __threadfence();
        __syncthreads();
        if (tid == 0) atomicAdd(&g_c_work, 1);
        return;                                          // exit -> frees slot
    }

    // ===== GEMM role: tile 64x128 =====
    extern __shared__ char sm[];
    int gid  = blockIdx.x - N_WORK;
    int bm0  = (gid >> 1) * BMT;
    int bn0  = (gid & 1) * BNT;
    int wid  = tid >> 5;
    int lane = tid & 31;
    int g    = lane >> 2;           // 0..7
    int t    = lane & 3;            // 0..3
    int wm   = (wid >> 2) * 32;     // 0 or 32
    int wn   = (wid & 3)  * 32;     // 0,32,64,96

    // A: 64 rows x 8 chunks = 512, 2/thread; B: 32 rows x 32 chunks = 1024, 4/thread
    int a_row0 = tid >> 3,         a_c4_0 = tid & 7;
    int a_row1 = (tid + 256) >> 3, a_c4_1 = (tid + 256) & 7;

    auto issue_tile = [&](int k0, int buf) {
        uint32_t sA = smem_u32(sm + buf * BUF_BYTES);
        uint32_t sB = sA + A_BYTES;
        {
            int gr = bm0 + a_row0;
            uint32_t dst = sA + (a_row0 * A_LD + a_c4_0 * 4) * 4;
            const float* srcp = &X[(size_t)gr * FDIM + k0 + a_c4_0 * 4];
            CP_ASYNC16(dst, srcp, (gr < NN) ? 16 : 0);
            gr = bm0 + a_row1;
            dst = sA + (a_row1 * A_LD + a_c4_1 * 4) * 4;
            srcp = &X[(size_t)gr * FDIM + k0 + a_c4_1 * 4];
            CP_ASYNC16(dst, srcp, (gr < NN) ? 16 : 0);
        }
        #pragma unroll
        for (int p = 0; p < 4; p++) {
            int id  = p * 256 + tid;
            int row = id >> 5;            // 0..31 (k)
            int c4  = id & 31;            // 0..31
            uint32_t dst = sB + (row * B_LD + c4 * 4) * 4;
            const float* srcp = &W[(size_t)(k0 + row) * FDIM + bn0 + c4 * 4];
            CP_ASYNC16(dst, srcp, 16);
        }
        CP_COMMIT();
    };

    float acc[2][4][4];
    #pragma unroll
    for (int mt = 0; mt < 2; mt++)
        #pragma unroll
        for (int nt = 0; nt < 4; nt++)
            #pragma unroll
            for (int q = 0; q < 4; q++) acc[mt][nt][q] = 0.0f;

    issue_tile(0, 0);

    #pragma unroll 1
    for (int ki = 0; ki < FDIM / BKT; ki++) {
        int buf = ki & 1;
        if (ki + 1 < FDIM / BKT) { issue_tile((ki + 1) * BKT, buf ^ 1); CP_WAIT(1); }
        else                     { CP_WAIT(0); }
        __syncthreads();

        const uint32_t* As = reinterpret_cast<const uint32_t*>(sm + buf * BUF_BYTES);
        const uint32_t* Bs = reinterpret_cast<const uint32_t*>(sm + buf * BUF_BYTES + A_BYTES);

        #pragma unroll
        for (int ks = 0; ks < BKT / 8; ks++) {
            int kb = ks * 8;
            uint32_t a[2][4];
            #pragma unroll
            for (int mt = 0; mt < 2; mt++) {
                int r0 = wm + mt * 16;
                a[mt][0] = rna(As[(r0 + g    ) * A_LD + kb + t    ]);
                a[mt][1] = rna(As[(r0 + g + 8) * A_LD + kb + t    ]);
                a[mt][2] = rna(As[(r0 + g    ) * A_LD + kb + t + 4]);
                a[mt][3] = rna(As[(r0 + g + 8) * A_LD + kb + t + 4]);
            }
            uint32_t b[4][2];
            #pragma unroll
            for (int nt = 0; nt < 4; nt++) {
                int col = wn + nt * 8 + g;
                b[nt][0] = rna(Bs[(kb + t    ) * B_LD + col]);
                b[nt][1] = rna(Bs[(kb + t + 4) * B_LD + col]);
            }
            #pragma unroll
            for (int mt = 0; mt < 2; mt++)
                #pragma unroll
                for (int nt = 0; nt < 4; nt++)
                    mma_tf32(acc[mt][nt], a[mt][0], a[mt][1], a[mt][2], a[mt][3],
                             b[nt][0], b[nt][1]);
        }
        __syncthreads();
    }

    // wait for workers' deg final, then pre-scale + store fp32/fp16 copies
    if (tid == 0)
        while (*(volatile int*)&g_c_work < N_WORK) __nanosleep(64);
    __syncthreads();
    __threadfence();

    #pragma unroll
    for (int mt = 0; mt < 2; mt++) {
        #pragma unroll
        for (int half = 0; half < 2; half++) {
            int gm = bm0 + wm + mt * 16 + g + half * 8;
            if (gm >= NN) continue;
            float dm = rsqrtf((float)(g_deg[gm] + 1));
            #pragma unroll
            for (int nt = 0; nt < 4; nt++) {
                float c0 = dm * acc[mt][nt][half * 2 + 0];
                float c1 = dm * acc[mt][nt][half * 2 + 1];
                int gc = bn0 + wn + nt * 8 + t * 2;
                *reinterpret_cast<float2*>(&g_Ps[(size_t)gm * FDIM + gc]) = make_float2(c0, c1);
                *reinterpret_cast<__half2*>(&g_Ph[(size_t)gm * FDIM + gc]) =
                    __float22half2_rn(make_float2(c0, c1));
            }
        }
    }
}

// ---------------- aggregation + ReLU: 1 warp/row, MLP-8, col prefetch ----------------
__global__ __launch_bounds__(256) void k_aggregate(float* __restrict__ out) {
    if (blockIdx.x == 0 && threadIdx.x == 0) { g_c_clear = 0; g_c_work = 0; }

    int row  = (blockIdx.x * blockDim.x + threadIdx.x) >> 5;
    int lane = threadIdx.x & 31;
    if (row >= NN) return;

    // self term (pre-scaled fp32), 8 cols/lane
    const float4* pr = reinterpret_cast<const float4*>(g_Ps + (size_t)row * FDIM) + lane * 2;
    float4 p0 = pr[0], p1 = pr[1];
    float a0 = p0.x, a1 = p0.y, a2 = p0.z, a3 = p0.w;
    float a4 = p1.x, a5 = p1.y, a6 = p1.z, a7 = p1.w;

    int len = g_rowcnt[row];
    if (len > CAP) len = CAP;
    const int*  cols = g_col + row * CAP;
    const int4* c4p  = reinterpret_cast<const int4*>(cols);

    int nq8 = len >> 3;
    int4 ca, cb;
    if (nq8 > 0) { ca = c4p[0]; cb = c4p[1]; }

    for (int q = 0; q < nq8; q++) {
        int4 cc = ca, cd = cb;
        if (q + 1 < nq8) { ca = c4p[2 * q + 2]; cb = c4p[2 * q + 3]; }
        uint4 h0 = *(reinterpret_cast<const uint4*>(g_Ph + (size_t)cc.x * FDIM) + lane);
        uint4 h1 = *(reinterpret_cast<const uint4*>(g_Ph + (size_t)cc.y * FDIM) + lane);
        uint4 h2 = *(reinterpret_cast<const uint4*>(g_Ph + (size_t)cc.z * FDIM) + lane);
        uint4 h3 = *(reinterpret_cast<const uint4*>(g_Ph + (size_t)cc.w * FDIM) + lane);
        uint4 h4 = *(reinterpret_cast<const uint4*>(g_Ph + (size_t)cd.x * FDIM) + lane);
        uint4 h5 = *(reinterpret_cast<const uint4*>(g_Ph + (size_t)cd.y * FDIM) + lane);
        uint4 h6 = *(reinterpret_cast<const uint4*>(g_Ph + (size_t)cd.z * FDIM) + lane);
        uint4 h7 = *(reinterpret_cast<const uint4*>(g_Ph + (size_t)cd.w * FDIM) + lane);
        #pragma unroll
        for (int pr2 = 0; pr2 < 4; pr2++) {
            const uint4& x = (pr2 == 0) ? h0 : (pr2 == 1) ? h2 : (pr2 == 2) ? h4 : h6;
            const uint4& y = (pr2 == 0) ? h1 : (pr2 == 1) ? h3 : (pr2 == 2) ? h5 : h7;
            __half2 s0 = __hadd2(*reinterpret_cast<const __half2*>(&x.x),
                                 *reinterpret_cast<const __half2*>(&y.x));
            __half2 s1 = __hadd2(*reinterpret_cast<const __half2*>(&x.y),
                                 *reinterpret_cast<const __half2*>(&y.y));
            __half2 s2 = __hadd2(*reinterpret_cast<const __half2*>(&x.z),
                                 *reinterpret_cast<const __half2*>(&y.z));
            __half2 s3 = __hadd2(*reinterpret_cast<const __half2*>(&x.w),
                                 *reinterpret_cast<const __half2*>(&y.w));
            float2 f;
            f = __half22float2(s0); a0 += f.x; a1 += f.y;
            f = __half22float2(s1); a2 += f.x; a3 += f.y;
            f = __half22float2(s2); a4 += f.x; a5 += f.y;
            f = __half22float2(s3); a6 += f.x; a7 += f.y;
        }
    }
    for (int i = nq8 * 8; i < len; i++) {
        uint4 h = *(reinterpret_cast<const uint4*>(g_Ph + (size_t)cols[i] * FDIM) + lane);
        float2 f;
        f = __half22float2(*reinterpret_cast<const __half2*>(&h.x)); a0 += f.x; a1 += f.y;
        f = __half22float2(*reinterpret_cast<const __half2*>(&h.y)); a2 += f.x; a3 += f.y;
        f = __half22float2(*reinterpret_cast<const __half2*>(&h.z)); a4 += f.x; a5 += f.y;
        f = __half22float2(*reinterpret_cast<const __half2*>(&h.w)); a6 += f.x; a7 += f.y;
    }

    float dr = rsqrtf((float)(g_deg[row] + 1));
    float4 o0 = make_float4(fmaxf(dr * a0, 0.f), fmaxf(dr * a1, 0.f),
                            fmaxf(dr * a2, 0.f), fmaxf(dr * a3, 0.f));
    float4 o1 = make_float4(fmaxf(dr * a4, 0.f), fmaxf(dr * a5, 0.f),
                            fmaxf(dr * a6, 0.f), fmaxf(dr * a7, 0.f));
    float4* po = reinterpret_cast<float4*>(out + (size_t)row * FDIM) + lane * 2;
    po[0] = o0; po[1] = o1;
}

// ---------------- launch ----------------
extern "C" void kernel_launch(void* const* d_in, const int* in_sizes, int n_in,
                              void* d_out, int out_size) {
    const float* X = (const float*)d_in[0];             // [10000, 256]
    const float* W = (const float*)d_in[1];             // [256, 256]
    const int*   E = (const int*)d_in[2];               // [2, 320000]
    const int* src = E;
    const int* tgt = E + NE;
    float* out = (float*)d_out;

    cudaFuncSetAttribute(k_fused, cudaFuncAttributeMaxDynamicSharedMemorySize, SMEM_TOTAL);

    k_fused<<<NBLK, THREADS, SMEM_TOTAL>>>(X, W, src, tgt);    // 452 CTAs, 3/SM
    k_aggregate<<<(NN * 32 + 255) / 256, 256>>>(out);          // 1250 blocks, 1 warp/row
}

// round 15
// speedup vs baseline: 1.1245x; 1.0442x over previous
#include <cuda_runtime.h>
#include <cuda_fp16.h>
#include <math.h>
#include <stdint.h>

// ---------------- problem constants ----------------
#define NN   10000
#define NE   320000
#define FDIM 256
#define CAP  128          // fixed per-row CSR capacity (E[deg]=32, max ~60)

#define BM_QUADS 781250   // 10000*10000 bits as uint4

// grid: 130 workers + 314 GEMM tiles = 444 = 148 SMs x 3 CTAs -> single wave, no tail
#define N_WORK  130
#define N_MT    157                       // ceil(10000/64)
#define N_GEMM  (N_MT * 2)                // 314 tiles of 64x128
#define NBLK    (N_WORK + N_GEMM)         // 444
#define THREADS 256

// ---------------- device scratch ----------------
__device__ uint4   g_bitmap4[BM_QUADS];
__device__ int     g_rowcnt[NN];
__device__ int     g_deg[NN];
__device__ int     g_col[NN * CAP];          // BYTE offsets into g_Ph (t*512)
__device__ float   g_Ps[NN * FDIM];          // dinv[m]*(X@W)[m], fp32 (self term)
__device__ __half  g_Ph[NN * FDIM];          // dinv[m]*(X@W)[m], fp16 (gather term)
__device__ int     g_c_clear;                // reset by k_aggregate
__device__ int     g_c_work;                 // reset by k_aggregate

// ---------------- GEMM config: 64x128x32, 8 warps 2(m)x4(n), warp 32x32 ----------------
#define BMT 64
#define BNT 128
#define BKT 32
#define A_LD (BKT + 4)                        // 36
#define B_LD (BNT + 8)                        // 136
#define A_BYTES (BMT * A_LD * 4)              // 9216
#define B_BYTES (BKT * B_LD * 4)              // 17408
#define BUF_BYTES (A_BYTES + B_BYTES)         // 26624
#define SMEM_TOTAL (2 * BUF_BYTES)            // 53248

__device__ __forceinline__ uint32_t smem_u32(const void* p) {
    uint32_t a;
    asm("{ .reg .u64 t; cvta.to.shared.u64 t, %1; cvt.u32.u64 %0, t; }" : "=r"(a) : "l"(p));
    return a;
}
#define CP_ASYNC16(dst, src, szr) \
    asm volatile("cp.async.cg.shared.global [%0], [%1], 16, %2;" \
        :: "r"(dst), "l"(src), "r"(szr))
#define CP_COMMIT() asm volatile("cp.async.commit_group;" ::: "memory")
#define CP_WAIT(n)  asm volatile("cp.async.wait_group %0;" :: "n"(n) : "memory")

__device__ __forceinline__ uint32_t rna(uint32_t x) {
    float r; asm("cvt.rna.tf32.f32 %0, %1;" : "=f"(r) : "f"(__uint_as_float(x)));
    return __float_as_uint(r);
}
__device__ __forceinline__ void mma_tf32(float c[4],
                                         uint32_t a0, uint32_t a1, uint32_t a2, uint32_t a3,
                                         uint32_t b0, uint32_t b1) {
    asm volatile(
        "mma.sync.aligned.m16n8k8.row.col.f32.tf32.tf32.f32 "
        "{%0,%1,%2,%3}, {%4,%5,%6,%7}, {%8,%9}, {%0,%1,%2,%3};"
        : "+f"(c[0]), "+f"(c[1]), "+f"(c[2]), "+f"(c[3])
        : "r"(a0), "r"(a1), "r"(a2), "r"(a3), "r"(b0), "r"(b1));
}

// ---------------- fused: worker CTAs (clear->dedup) || GEMM CTAs ----------------
__global__ __launch_bounds__(THREADS, 3) void k_fused(const float* __restrict__ X,
                                                      const float* __restrict__ W,
                                                      const int* __restrict__ src,
                                                      const int* __restrict__ tgt) {
    int tid = threadIdx.x;

    if (blockIdx.x < N_WORK) {
        // ===== worker role: clear, barrier(workers), dedup + CSR fill =====
        int gt = blockIdx.x * THREADS + tid;
        const int nthr = N_WORK * THREADS;               // 33280

        uint4 z = make_uint4(0u, 0u, 0u, 0u);
        for (int w = gt; w < BM_QUADS; w += nthr) g_bitmap4[w] = z;
        for (int j = gt; j < NN; j += nthr) { g_rowcnt[j] = 0; g_deg[j] = 0; }
        __threadfence();
        __syncthreads();
        if (tid == 0) {
            atomicAdd(&g_c_clear, 1);
            while (*(volatile int*)&g_c_clear < N_WORK) __nanosleep(64);
        }
        __syncthreads();

        unsigned int* bm = reinterpret_cast<unsigned int*>(g_bitmap4);
        const int nq = NE / 4;
        for (int i = gt; i < nq; i += nthr) {
            int4 s4 = reinterpret_cast<const int4*>(src)[i];
            int4 t4 = reinterpret_cast<const int4*>(tgt)[i];
            int ss[4] = {s4.x, s4.y, s4.z, s4.w};
            int tt[4] = {t4.x, t4.y, t4.z, t4.w};
            #pragma unroll
            for (int j = 0; j < 4; j++) {
                int s = ss[j], t = tt[j];
                unsigned int bit  = (unsigned int)s * (unsigned int)NN + (unsigned int)t;
                unsigned int word = bit >> 5;
                unsigned int mask = 1u << (bit & 31u);
                unsigned int old  = atomicOr(&bm[word], mask);
                if (!(old & mask)) {
                    int pos = atomicAdd(&g_rowcnt[s], 1);
                    if (pos < CAP) g_col[s * CAP + pos] = t * (FDIM * 2);  // byte offset
                    atomicAdd(&g_deg[t], 1);
                }
            }
        }
        __threadfence();
        __syncthreads();
        if (tid == 0) atomicAdd(&g_c_work, 1);
        return;
    }

    // ===== GEMM role: tile 64x128 =====
    extern __shared__ char sm[];
    int gid  = blockIdx.x - N_WORK;
    int bm0  = (gid >> 1) * BMT;
    int bn0  = (gid & 1) * BNT;
    int wid  = tid >> 5;
    int lane = tid & 31;
    int g    = lane >> 2;           // 0..7
    int t    = lane & 3;            // 0..3
    int wm   = (wid >> 2) * 32;     // 0 or 32
    int wn   = (wid & 3)  * 32;     // 0,32,64,96

    int a_row0 = tid >> 3,         a_c4_0 = tid & 7;
    int a_row1 = (tid + 256) >> 3, a_c4_1 = (tid + 256) & 7;

    auto issue_tile = [&](int k0, int buf) {
        uint32_t sA = smem_u32(sm + buf * BUF_BYTES);
        uint32_t sB = sA + A_BYTES;
        {
            int gr = bm0 + a_row0;
            uint32_t dst = sA + (a_row0 * A_LD + a_c4_0 * 4) * 4;
            const float* srcp = &X[(size_t)gr * FDIM + k0 + a_c4_0 * 4];
            CP_ASYNC16(dst, srcp, (gr < NN) ? 16 : 0);
            gr = bm0 + a_row1;
            dst = sA + (a_row1 * A_LD + a_c4_1 * 4) * 4;
            srcp = &X[(size_t)gr * FDIM + k0 + a_c4_1 * 4];
            CP_ASYNC16(dst, srcp, (gr < NN) ? 16 : 0);
        }
        #pragma unroll
        for (int p = 0; p < 4; p++) {
            int id  = p * 256 + tid;
            int row = id >> 5;            // 0..31 (k)
            int c4  = id & 31;            // 0..31
            uint32_t dst = sB + (row * B_LD + c4 * 4) * 4;
            const float* srcp = &W[(size_t)(k0 + row) * FDIM + bn0 + c4 * 4];
            CP_ASYNC16(dst, srcp, 16);
        }
        CP_COMMIT();
    };

    float acc[2][4][4];
    #pragma unroll
    for (int mt = 0; mt < 2; mt++)
        #pragma unroll
        for (int nt = 0; nt < 4; nt++)
            #pragma unroll
            for (int q = 0; q < 4; q++) acc[mt][nt][q] = 0.0f;

    issue_tile(0, 0);

    #pragma unroll 1
    for (int ki = 0; ki < FDIM / BKT; ki++) {
        int buf = ki & 1;
        if (ki + 1 < FDIM / BKT) { issue_tile((ki + 1) * BKT, buf ^ 1); CP_WAIT(1); }
        else                     { CP_WAIT(0); }
        __syncthreads();

        const uint32_t* As = reinterpret_cast<const uint32_t*>(sm + buf * BUF_BYTES);
        const uint32_t* Bs = reinterpret_cast<const uint32_t*>(sm + buf * BUF_BYTES + A_BYTES);

        #pragma unroll
        for (int ks = 0; ks < BKT / 8; ks++) {
            int kb = ks * 8;
            uint32_t a[2][4];
            #pragma unroll
            for (int mt = 0; mt < 2; mt++) {
                int r0 = wm + mt * 16;
                a[mt][0] = rna(As[(r0 + g    ) * A_LD + kb + t    ]);
                a[mt][1] = rna(As[(r0 + g + 8) * A_LD + kb + t    ]);
                a[mt][2] = rna(As[(r0 + g    ) * A_LD + kb + t + 4]);
                a[mt][3] = rna(As[(r0 + g + 8) * A_LD + kb + t + 4]);
            }
            uint32_t b[4][2];
            #pragma unroll
            for (int nt = 0; nt < 4; nt++) {
                int col = wn + nt * 8 + g;
                b[nt][0] = rna(Bs[(kb + t    ) * B_LD + col]);
                b[nt][1] = rna(Bs[(kb + t + 4) * B_LD + col]);
            }
            #pragma unroll
            for (int mt = 0; mt < 2; mt++)
                #pragma unroll
                for (int nt = 0; nt < 4; nt++)
                    mma_tf32(acc[mt][nt], a[mt][0], a[mt][1], a[mt][2], a[mt][3],
                             b[nt][0], b[nt][1]);
        }
        __syncthreads();
    }

    // wait for workers' deg final, then pre-scale + store fp32/fp16 copies
    if (tid == 0)
        while (*(volatile int*)&g_c_work < N_WORK) __nanosleep(64);
    __syncthreads();
    __threadfence();

    #pragma unroll
    for (int mt = 0; mt < 2; mt++) {
        #pragma unroll
        for (int half = 0; half < 2; half++) {
            int gm = bm0 + wm + mt * 16 + g + half * 8;
            if (gm >= NN) continue;
            float dm = rsqrtf((float)(g_deg[gm] + 1));
            #pragma unroll
            for (int nt = 0; nt < 4; nt++) {
                float c0 = dm * acc[mt][nt][half * 2 + 0];
                float c1 = dm * acc[mt][nt][half * 2 + 1];
                int gc = bn0 + wn + nt * 8 + t * 2;
                *reinterpret_cast<float2*>(&g_Ps[(size_t)gm * FDIM + gc]) = make_float2(c0, c1);
                *reinterpret_cast<__half2*>(&g_Ph[(size_t)gm * FDIM + gc]) =
                    __float22half2_rn(make_float2(c0, c1));
            }
        }
    }
}

// ---------------- aggregation + ReLU: 1 warp/row, MLP-8, 2-level HADD2 ----------------
__device__ __forceinline__ __half2 h2(const uint32_t& u) {
    return *reinterpret_cast<const __half2*>(&u);
}

__global__ __launch_bounds__(256, 5) void k_aggregate(float* __restrict__ out) {
    if (blockIdx.x == 0 && threadIdx.x == 0) { g_c_clear = 0; g_c_work = 0; }

    int row  = (blockIdx.x * blockDim.x + threadIdx.x) >> 5;
    int lane = threadIdx.x & 31;
    if (row >= NN) return;

    // per-lane base pointer into g_Ph (byte offsets come from g_col)
    const char* basel = reinterpret_cast<const char*>(g_Ph) + lane * 16;

    // self term (pre-scaled fp32), 8 cols/lane
    const float4* pr = reinterpret_cast<const float4*>(g_Ps + (size_t)row * FDIM) + lane * 2;
    float4 p0 = pr[0], p1 = pr[1];
    float a0 = p0.x, a1 = p0.y, a2 = p0.z, a3 = p0.w;
    float a4 = p1.x, a5 = p1.y, a6 = p1.z, a7 = p1.w;

    int len = g_rowcnt[row];
    if (len > CAP) len = CAP;
    const int*  cols = g_col + row * CAP;
    const int4* c4p  = reinterpret_cast<const int4*>(cols);

    int nq8 = len >> 3;
    int4 ca, cb;
    if (nq8 > 0) { ca = c4p[0]; cb = c4p[1]; }

    for (int q = 0; q < nq8; q++) {
        int4 cc = ca, cd = cb;
        if (q + 1 < nq8) { ca = c4p[2 * q + 2]; cb = c4p[2 * q + 3]; }
        // 8 independent gathers (MLP 8), address = basel + byte_offset
        uint4 h0 = *reinterpret_cast<const uint4*>(basel + cc.x);
        uint4 h1 = *reinterpret_cast<const uint4*>(basel + cc.y);
        uint4 h2v = *reinterpret_cast<const uint4*>(basel + cc.z);
        uint4 h3 = *reinterpret_cast<const uint4*>(basel + cc.w);
        uint4 h4 = *reinterpret_cast<const uint4*>(basel + cd.x);
        uint4 h5 = *reinterpret_cast<const uint4*>(basel + cd.y);
        uint4 h6 = *reinterpret_cast<const uint4*>(basel + cd.z);
        uint4 h7 = *reinterpret_cast<const uint4*>(basel + cd.w);
        // 2-level fp16 pairing (4-term trees), then fp32 accumulate
        __half2 q0x = __hadd2(__hadd2(h2(h0.x), h2(h1.x)), __hadd2(h2(h2v.x), h2(h3.x)));
        __half2 q0y = __hadd2(__hadd2(h2(h0.y), h2(h1.y)), __hadd2(h2(h2v.y), h2(h3.y)));
        __half2 q0z = __hadd2(__hadd2(h2(h0.z), h2(h1.z)), __hadd2(h2(h2v.z), h2(h3.z)));
        __half2 q0w = __hadd2(__hadd2(h2(h0.w), h2(h1.w)), __hadd2(h2(h2v.w), h2(h3.w)));
        __half2 q1x = __hadd2(__hadd2(h2(h4.x), h2(h5.x)), __hadd2(h2(h6.x), h2(h7.x)));
        __half2 q1y = __hadd2(__hadd2(h2(h4.y), h2(h5.y)), __hadd2(h2(h6.y), h2(h7.y)));
        __half2 q1z = __hadd2(__hadd2(h2(h4.z), h2(h5.z)), __hadd2(h2(h6.z), h2(h7.z)));
        __half2 q1w = __hadd2(__hadd2(h2(h4.w), h2(h5.w)), __hadd2(h2(h6.w), h2(h7.w)));
        float2 f;
        f = __half22float2(q0x); a0 += f.x; a1 += f.y;
        f = __half22float2(q0y); a2 += f.x; a3 += f.y;
        f = __half22float2(q0z); a4 += f.x; a5 += f.y;
        f = __half22float2(q0w); a6 += f.x; a7 += f.y;
        f = __half22float2(q1x); a0 += f.x; a1 += f.y;
        f = __half22float2(q1y); a2 += f.x; a3 += f.y;
        f = __half22float2(q1z); a4 += f.x; a5 += f.y;
        f = __half22float2(q1w); a6 += f.x; a7 += f.y;
    }
    for (int i = nq8 * 8; i < len; i++) {
        uint4 h = *reinterpret_cast<const uint4*>(basel + cols[i]);
        float2 f;
        f = __half22float2(h2(h.x)); a0 += f.x; a1 += f.y;
        f = __half22float2(h2(h.y)); a2 += f.x; a3 += f.y;
        f = __half22float2(h2(h.z)); a4 += f.x; a5 += f.y;
        f = __half22float2(h2(h.w)); a6 += f.x; a7 += f.y;
    }

    float dr = rsqrtf((float)(g_deg[row] + 1));
    float4 o0 = make_float4(fmaxf(dr * a0, 0.f), fmaxf(dr * a1, 0.f),
                            fmaxf(dr * a2, 0.f), fmaxf(dr * a3, 0.f));
    float4 o1 = make_float4(fmaxf(dr * a4, 0.f), fmaxf(dr * a5, 0.f),
                            fmaxf(dr * a6, 0.f), fmaxf(dr * a7, 0.f));
    float4* po = reinterpret_cast<float4*>(out + (size_t)row * FDIM) + lane * 2;
    po[0] = o0; po[1] = o1;
}

// ---------------- launch ----------------
extern "C" void kernel_launch(void* const* d_in, const int* in_sizes, int n_in,
                              void* d_out, int out_size) {
    const float* X = (const float*)d_in[0];             // [10000, 256]
    const float* W = (const float*)d_in[1];             // [256, 256]
    const int*   E = (const int*)d_in[2];               // [2, 320000]
    const int* src = E;
    const int* tgt = E + NE;
    float* out = (float*)d_out;

    cudaFuncSetAttribute(k_fused, cudaFuncAttributeMaxDynamicSharedMemorySize, SMEM_TOTAL);

    k_fused<<<NBLK, THREADS, SMEM_TOTAL>>>(X, W, src, tgt);    // 444 CTAs = 148x3, one wave
    k_aggregate<<<(NN * 32 + 255) / 256, 256>>>(out);          // 1250 blocks, 1 warp/row
}

// round 17
// speedup vs baseline: 1.1298x; 1.0047x over previous
#include <cuda_runtime.h>
#include <cuda_fp16.h>
#include <math.h>
#include <stdint.h>

// ---------------- problem constants ----------------
#define NN   10000
#define NE   320000
#define FDIM 256
#define CAP  128          // fixed per-row CSR capacity (E[deg]=32, max ~60)

#define BM_QUADS 781250   // 10000*10000 bits as uint4

// grid: 130 workers + 314 GEMM tiles = 444 = 148 SMs x 3 CTAs -> single wave, no tail
#define N_WORK  130
#define N_MT    157                       // ceil(10000/64)
#define N_GEMM  (N_MT * 2)                // 314 tiles of 64x128
#define NBLK    (N_WORK + N_GEMM)         // 444
#define THREADS 256

// ---------------- device scratch ----------------
__device__ uint4   g_bitmap4[BM_QUADS];
__device__ int     g_rowcnt[NN];
__device__ int     g_deg[NN];
__device__ int     g_col[NN * CAP];          // BYTE offsets into g_Ph (t*512)
__device__ float   g_Ps[NN * FDIM];          // dinv[m]*(X@W)[m], fp32 (self term)
__device__ __half  g_Ph[NN * FDIM];          // dinv[m]*(X@W)[m], fp16 (gather term)
__device__ int     g_c_clear;                // reset by k_aggregate
__device__ int     g_c_work;                 // reset by k_aggregate

// ---------------- GEMM config: 64x128x32, 8 warps 2(m)x4(n), warp 32x32 ----------------
#define BMT 64
#define BNT 128
#define BKT 32
#define A_LD (BKT + 4)                        // 36
#define B_LD (BNT + 8)                        // 136
#define A_BYTES (BMT * A_LD * 4)              // 9216
#define B_BYTES (BKT * B_LD * 4)              // 17408
#define BUF_BYTES (A_BYTES + B_BYTES)         // 26624
#define SMEM_TOTAL (2 * BUF_BYTES)            // 53248

__device__ __forceinline__ uint32_t smem_u32(const void* p) {
    uint32_t a;
    asm("{ .reg .u64 t; cvta.to.shared.u64 t, %1; cvt.u32.u64 %0, t; }" : "=r"(a) : "l"(p));
    return a;
}
#define CP_ASYNC16(dst, src, szr) \
    asm volatile("cp.async.cg.shared.global [%0], [%1], 16, %2;" \
        :: "r"(dst), "l"(src), "r"(szr))
#define CP_COMMIT() asm volatile("cp.async.commit_group;" ::: "memory")
#define CP_WAIT(n)  asm volatile("cp.async.wait_group %0;" :: "n"(n) : "memory")

__device__ __forceinline__ uint32_t rna(uint32_t x) {
    float r; asm("cvt.rna.tf32.f32 %0, %1;" : "=f"(r) : "f"(__uint_as_float(x)));
    return __float_as_uint(r);
}
__device__ __forceinline__ void mma_tf32(float c[4],
                                         uint32_t a0, uint32_t a1, uint32_t a2, uint32_t a3,
                                         uint32_t b0, uint32_t b1) {
    asm volatile(
        "mma.sync.aligned.m16n8k8.row.col.f32.tf32.tf32.f32 "
        "{%0,%1,%2,%3}, {%4,%5,%6,%7}, {%8,%9}, {%0,%1,%2,%3};"
        : "+f"(c[0]), "+f"(c[1]), "+f"(c[2]), "+f"(c[3])
        : "r"(a0), "r"(a1), "r"(a2), "r"(a3), "r"(b0), "r"(b1));
}

// ---------------- fused: worker CTAs (clear->dedup) || GEMM CTAs (unchanged, R15) ----------------
__global__ __launch_bounds__(THREADS, 3) void k_fused(const float* __restrict__ X,
                                                      const float* __restrict__ W,
                                                      const int* __restrict__ src,
                                                      const int* __restrict__ tgt) {
    int tid = threadIdx.x;

    if (blockIdx.x < N_WORK) {
        int gt = blockIdx.x * THREADS + tid;
        const int nthr = N_WORK * THREADS;

        uint4 z = make_uint4(0u, 0u, 0u, 0u);
        for (int w = gt; w < BM_QUADS; w += nthr) g_bitmap4[w] = z;
        for (int j = gt; j < NN; j += nthr) { g_rowcnt[j] = 0; g_deg[j] = 0; }
        __threadfence();
        __syncthreads();
        if (tid == 0) {
            atomicAdd(&g_c_clear, 1);
            while (*(volatile int*)&g_c_clear < N_WORK) __nanosleep(64);
        }
        __syncthreads();

        unsigned int* bm = reinterpret_cast<unsigned int*>(g_bitmap4);
        const int nq = NE / 4;
        for (int i = gt; i < nq; i += nthr) {
            int4 s4 = reinterpret_cast<const int4*>(src)[i];
            int4 t4 = reinterpret_cast<const int4*>(tgt)[i];
            int ss[4] = {s4.x, s4.y, s4.z, s4.w};
            int tt[4] = {t4.x, t4.y, t4.z, t4.w};
            #pragma unroll
            for (int j = 0; j < 4; j++) {
                int s = ss[j], t = tt[j];
                unsigned int bit  = (unsigned int)s * (unsigned int)NN + (unsigned int)t;
                unsigned int word = bit >> 5;
                unsigned int mask = 1u << (bit & 31u);
                unsigned int old  = atomicOr(&bm[word], mask);
                if (!(old & mask)) {
                    int pos = atomicAdd(&g_rowcnt[s], 1);
                    if (pos < CAP) g_col[s * CAP + pos] = t * (FDIM * 2);  // byte offset
                    atomicAdd(&g_deg[t], 1);
                }
            }
        }
        __threadfence();
        __syncthreads();
        if (tid == 0) atomicAdd(&g_c_work, 1);
        return;
    }

    extern __shared__ char sm[];
    int gid  = blockIdx.x - N_WORK;
    int bm0  = (gid >> 1) * BMT;
    int bn0  = (gid & 1) * BNT;
    int wid  = tid >> 5;
    int lane = tid & 31;
    int g    = lane >> 2;
    int t    = lane & 3;
    int wm   = (wid >> 2) * 32;
    int wn   = (wid & 3)  * 32;

    int a_row0 = tid >> 3,         a_c4_0 = tid & 7;
    int a_row1 = (tid + 256) >> 3, a_c4_1 = (tid + 256) & 7;

    auto issue_tile = [&](int k0, int buf) {
        uint32_t sA = smem_u32(sm + buf * BUF_BYTES);
        uint32_t sB = sA + A_BYTES;
        {
            int gr = bm0 + a_row0;
            uint32_t dst = sA + (a_row0 * A_LD + a_c4_0 * 4) * 4;
            const float* srcp = &X[(size_t)gr * FDIM + k0 + a_c4_0 * 4];
            CP_ASYNC16(dst, srcp, (gr < NN) ? 16 : 0);
            gr = bm0 + a_row1;
            dst = sA + (a_row1 * A_LD + a_c4_1 * 4) * 4;
            srcp = &X[(size_t)gr * FDIM + k0 + a_c4_1 * 4];
            CP_ASYNC16(dst, srcp, (gr < NN) ? 16 : 0);
        }
        #pragma unroll
        for (int p = 0; p < 4; p++) {
            int id  = p * 256 + tid;
            int row = id >> 5;
            int c4  = id & 31;
            uint32_t dst = sB + (row * B_LD + c4 * 4) * 4;
            const float* srcp = &W[(size_t)(k0 + row) * FDIM + bn0 + c4 * 4];
            CP_ASYNC16(dst, srcp, 16);
        }
        CP_COMMIT();
    };

    float acc[2][4][4];
    #pragma unroll
    for (int mt = 0; mt < 2; mt++)
        #pragma unroll
        for (int nt = 0; nt < 4; nt++)
            #pragma unroll
            for (int q = 0; q < 4; q++) acc[mt][nt][q] = 0.0f;

    issue_tile(0, 0);

    #pragma unroll 1
    for (int ki = 0; ki < FDIM / BKT; ki++) {
        int buf = ki & 1;
        if (ki + 1 < FDIM / BKT) { issue_tile((ki + 1) * BKT, buf ^ 1); CP_WAIT(1); }
        else                     { CP_WAIT(0); }
        __syncthreads();

        const uint32_t* As = reinterpret_cast<const uint32_t*>(sm + buf * BUF_BYTES);
        const uint32_t* Bs = reinterpret_cast<const uint32_t*>(sm + buf * BUF_BYTES + A_BYTES);

        #pragma unroll
        for (int ks = 0; ks < BKT / 8; ks++) {
            int kb = ks * 8;
            uint32_t a[2][4];
            #pragma unroll
            for (int mt = 0; mt < 2; mt++) {
                int r0 = wm + mt * 16;
                a[mt][0] = rna(As[(r0 + g    ) * A_LD + kb + t    ]);
                a[mt][1] = rna(As[(r0 + g + 8) * A_LD + kb + t    ]);
                a[mt][2] = rna(As[(r0 + g    ) * A_LD + kb + t + 4]);
                a[mt][3] = rna(As[(r0 + g + 8) * A_LD + kb + t + 4]);
            }
            uint32_t b[4][2];
            #pragma unroll
            for (int nt = 0; nt < 4; nt++) {
                int col = wn + nt * 8 + g;
                b[nt][0] = rna(Bs[(kb + t    ) * B_LD + col]);
                b[nt][1] = rna(Bs[(kb + t + 4) * B_LD + col]);
            }
            #pragma unroll
            for (int mt = 0; mt < 2; mt++)
                #pragma unroll
                for (int nt = 0; nt < 4; nt++)
                    mma_tf32(acc[mt][nt], a[mt][0], a[mt][1], a[mt][2], a[mt][3],
                             b[nt][0], b[nt][1]);
        }
        __syncthreads();
    }

    if (tid == 0)
        while (*(volatile int*)&g_c_work < N_WORK) __nanosleep(64);
    __syncthreads();
    __threadfence();

    #pragma unroll
    for (int mt = 0; mt < 2; mt++) {
        #pragma unroll
        for (int half = 0; half < 2; half++) {
            int gm = bm0 + wm + mt * 16 + g + half * 8;
            if (gm >= NN) continue;
            float dm = rsqrtf((float)(g_deg[gm] + 1));
            #pragma unroll
            for (int nt = 0; nt < 4; nt++) {
                float c0 = dm * acc[mt][nt][half * 2 + 0];
                float c1 = dm * acc[mt][nt][half * 2 + 1];
                int gc = bn0 + wn + nt * 8 + t * 2;
                *reinterpret_cast<float2*>(&g_Ps[(size_t)gm * FDIM + gc]) = make_float2(c0, c1);
                *reinterpret_cast<__half2*>(&g_Ph[(size_t)gm * FDIM + gc]) =
                    __float22half2_rn(make_float2(c0, c1));
            }
        }
    }
}

// ---------------- aggregation: cp.async double-buffered gather, 1 warp/row ----------------
// stage = 8 neighbors x 512B = 4KB, 2 stages/warp (8KB), 4 warps/CTA = 32KB smem.
// One commit group per stage; every wait is wait_group(1) except the final wait_group(0).
// No zero-size dummies (cp.async src-size<16 zero-FILLS; R16 lesson).
#define ST_NB    8
#define ST_BYTES (ST_NB * 512)               // 4096
#define AG_WARPS 4
#define AG_SMEM  (AG_WARPS * 2 * ST_BYTES)   // 32768

__device__ __forceinline__ __half2 h2(const uint32_t& u) {
    return *reinterpret_cast<const __half2*>(&u);
}

__global__ __launch_bounds__(128) void k_aggregate(float* __restrict__ out) {
    __shared__ __align__(16) char sbuf[AG_SMEM];
    if (blockIdx.x == 0 && threadIdx.x == 0) { g_c_clear = 0; g_c_work = 0; }

    int wid  = threadIdx.x >> 5;
    int lane = threadIdx.x & 31;
    int row  = blockIdx.x * AG_WARPS + wid;
    if (row >= NN) return;

    char*    swarp   = sbuf + wid * (2 * ST_BYTES) + lane * 16;   // lane's 16B slot
    uint32_t swarp_u = smem_u32(swarp);
    const char* baseg = reinterpret_cast<const char*>(g_Ph) + lane * 16;

    // self term (pre-scaled fp32)
    const float4* pr = reinterpret_cast<const float4*>(g_Ps + (size_t)row * FDIM) + lane * 2;
    float4 p0 = pr[0], p1 = pr[1];
    float a0 = p0.x, a1 = p0.y, a2 = p0.z, a3 = p0.w;
    float a4 = p1.x, a5 = p1.y, a6 = p1.z, a7 = p1.w;

    int len = g_rowcnt[row];
    if (len > CAP) len = CAP;
    const int*  cols = g_col + row * CAP;        // byte offsets
    const int4* c4p  = reinterpret_cast<const int4*>(cols);

    int nst = len >> 3;                          // full stages of 8

    auto issue_stage = [&](int st) {             // st-th stage -> slot st&1
        uint32_t dst = swarp_u + (st & 1) * ST_BYTES;
        int4 c0 = c4p[st * 2], c1 = c4p[st * 2 + 1];
        CP_ASYNC16(dst,        baseg + c0.x, 16);
        CP_ASYNC16(dst + 512,  baseg + c0.y, 16);
        CP_ASYNC16(dst + 1024, baseg + c0.z, 16);
        CP_ASYNC16(dst + 1536, baseg + c0.w, 16);
        CP_ASYNC16(dst + 2048, baseg + c1.x, 16);
        CP_ASYNC16(dst + 2560, baseg + c1.y, 16);
        CP_ASYNC16(dst + 3072, baseg + c1.z, 16);
        CP_ASYNC16(dst + 3584, baseg + c1.w, 16);
        CP_COMMIT();
    };

    if (nst > 0) {
        issue_stage(0);
        if (nst > 1) issue_stage(1);

        for (int q = 0; q < nst; q++) {
            if (q == nst - 1) { CP_WAIT(0); } else { CP_WAIT(1); }   // stage q complete
            const char* s = swarp + (q & 1) * ST_BYTES;
            uint4 h0 = *reinterpret_cast<const uint4*>(s);
            uint4 h1 = *reinterpret_cast<const uint4*>(s + 512);
            uint4 hv = *reinterpret_cast<const uint4*>(s + 1024);
            uint4 h3 = *reinterpret_cast<const uint4*>(s + 1536);
            uint4 h4 = *reinterpret_cast<const uint4*>(s + 2048);
            uint4 h5 = *reinterpret_cast<const uint4*>(s + 2560);
            uint4 h6 = *reinterpret_cast<const uint4*>(s + 3072);
            uint4 h7 = *reinterpret_cast<const uint4*>(s + 3584);

            if (q + 2 < nst) issue_stage(q + 2);   // refill consumed slot

            // 2-level HADD2 trees (two groups of 4), fp32 accumulate — R15 numerics
            __half2 q0x = __hadd2(__hadd2(h2(h0.x), h2(h1.x)), __hadd2(h2(hv.x), h2(h3.x)));
            __half2 q0y = __hadd2(__hadd2(h2(h0.y), h2(h1.y)), __hadd2(h2(hv.y), h2(h3.y)));
            __half2 q0z = __hadd2(__hadd2(h2(h0.z), h2(h1.z)), __hadd2(h2(hv.z), h2(h3.z)));
            __half2 q0w = __hadd2(__hadd2(h2(h0.w), h2(h1.w)), __hadd2(h2(hv.w), h2(h3.w)));
            __half2 q1x = __hadd2(__hadd2(h2(h4.x), h2(h5.x)), __hadd2(h2(h6.x), h2(h7.x)));
            __half2 q1y = __hadd2(__hadd2(h2(h4.y), h2(h5.y)), __hadd2(h2(h6.y), h2(h7.y)));
            __half2 q1z = __hadd2(__hadd2(h2(h4.z), h2(h5.z)), __hadd2(h2(h6.z), h2(h7.z)));
            __half2 q1w = __hadd2(__hadd2(h2(h4.w), h2(h5.w)), __hadd2(h2(h6.w), h2(h7.w)));
            float2 f;
            f = __half22float2(q0x); a0 += f.x; a1 += f.y;
            f = __half22float2(q0y); a2 += f.x; a3 += f.y;
            f = __half22float2(q0z); a4 += f.x; a5 += f.y;
            f = __half22float2(q0w); a6 += f.x; a7 += f.y;
            f = __half22float2(q1x); a0 += f.x; a1 += f.y;
            f = __half22float2(q1y); a2 += f.x; a3 += f.y;
            f = __half22float2(q1z); a4 += f.x; a5 += f.y;
            f = __half22float2(q1w); a6 += f.x; a7 += f.y;
        }
    }

    // tail neighbors (<8): direct LDG, plain fp32
    for (int i = nst * 8; i < len; i++) {
        uint4 h = *reinterpret_cast<const uint4*>(baseg + cols[i]);
        float2 f;
        f = __half22float2(h2(h.x)); a0 += f.x; a1 += f.y;
        f = __half22float2(h2(h.y)); a2 += f.x; a3 += f.y;
        f = __half22float2(h2(h.z)); a4 += f.x; a5 += f.y;
        f = __half22float2(h2(h.w)); a6 += f.x; a7 += f.y;
    }

    float dr = rsqrtf((float)(g_deg[row] + 1));
    float4 o0 = make_float4(fmaxf(dr * a0, 0.f), fmaxf(dr * a1, 0.f),
                            fmaxf(dr * a2, 0.f), fmaxf(dr * a3, 0.f));
    float4 o1 = make_float4(fmaxf(dr * a4, 0.f), fmaxf(dr * a5, 0.f),
                            fmaxf(dr * a6, 0.f), fmaxf(dr * a7, 0.f));
    float4* po = reinterpret_cast<float4*>(out + (size_t)row * FDIM) + lane * 2;
    po[0] = o0; po[1] = o1;
}

// ---------------- launch ----------------
extern "C" void kernel_launch(void* const* d_in, const int* in_sizes, int n_in,
                              void* d_out, int out_size) {
    const float* X = (const float*)d_in[0];             // [10000, 256]
    const float* W = (const float*)d_in[1];             // [256, 256]
    const int*   E = (const int*)d_in[2];               // [2, 320000]
    const int* src = E;
    const int* tgt = E + NE;
    float* out = (float*)d_out;

    cudaFuncSetAttribute(k_fused, cudaFuncAttributeMaxDynamicSharedMemorySize, SMEM_TOTAL);

    k_fused<<<NBLK, THREADS, SMEM_TOTAL>>>(X, W, src, tgt);    // 444 CTAs = 148x3, one wave
    k_aggregate<<<(NN + AG_WARPS - 1) / AG_WARPS, 128>>>(out); // 2500 blocks, 1 warp/row
}